// round 4
// baseline (speedup 1.0000x reference)
#include <cuda_runtime.h>
#include <math.h>
#include <float.h>

#define D_FEAT 256
#define BATCH  4096
#define NVROW  (D_FEAT / 4)   // 64 float4 per full row
#define CGN    32             // float4-columns per CTA (half a row)

// Segment boundary table: g_offsets[s] = first row index with membership >= s.
__device__ int g_offsets[BATCH + 1];

__global__ void boundary_kernel(const int* __restrict__ mem, int n_atoms)
{
    int i = blockIdx.x * blockDim.x + threadIdx.x;
    if (i >= n_atoms) return;
    int cur  = mem[i];
    int prev = (i == 0) ? -1 : mem[i - 1];
    for (int s = prev + 1; s <= cur; ++s) g_offsets[s] = i;
    if (i == n_atoms - 1) {
        for (int s = cur + 1; s <= BATCH; ++s) g_offsets[s] = n_atoms;
    }
}

// Two CTAs per segment (one per 128-column half) -> 8192 CTAs, fine-grained
// enough that wave quantization over 148 SMs x 8 resident is ~1%.
// Thread t: cg = t & 31 (float4 column within half), ro = t >> 5 (8 row groups,
// row stride 8). Register float4 sum/max, smem reduce across the 8 row groups,
// tanh, float4 stores.
__global__ __launch_bounds__(256, 8)
void graph_gather_kernel(const float4* __restrict__ feat,
                         float* __restrict__ out)
{
    const int seg  = blockIdx.x >> 1;
    const int half = blockIdx.x & 1;

    const int start = g_offsets[seg];
    const int cnt   = g_offsets[seg + 1] - start;

    const int cg = threadIdx.x & (CGN - 1);
    const int ro = threadIdx.x >> 5;

    const float4* __restrict__ p =
        feat + (size_t)start * NVROW + half * CGN + cg;

    float4 s = make_float4(0.f, 0.f, 0.f, 0.f);
    float4 m = make_float4(-INFINITY, -INFINITY, -INFINITY, -INFINITY);

    int r = ro;
    // 2-wide unroll: two independent 16B loads in flight per thread.
    for (; r + 8 < cnt; r += 16) {
        float4 a = p[(size_t)r * NVROW];
        float4 b = p[(size_t)(r + 8) * NVROW];
        s.x += a.x + b.x;  s.y += a.y + b.y;
        s.z += a.z + b.z;  s.w += a.w + b.w;
        m.x = fmaxf(m.x, fmaxf(a.x, b.x));
        m.y = fmaxf(m.y, fmaxf(a.y, b.y));
        m.z = fmaxf(m.z, fmaxf(a.z, b.z));
        m.w = fmaxf(m.w, fmaxf(a.w, b.w));
    }
    if (r < cnt) {
        float4 a = p[(size_t)r * NVROW];
        s.x += a.x; s.y += a.y; s.z += a.z; s.w += a.w;
        m.x = fmaxf(m.x, a.x); m.y = fmaxf(m.y, a.y);
        m.z = fmaxf(m.z, a.z); m.w = fmaxf(m.w, a.w);
    }

    __shared__ float4 ssum[256];
    __shared__ float4 smax[256];
    ssum[threadIdx.x] = s;
    smax[threadIdx.x] = m;
    __syncthreads();

    // Threads 0-31 reduce sums, threads 32-63 reduce maxes (parallel halves).
    if (threadIdx.x < 64) {
        const int col   = threadIdx.x & (CGN - 1);
        const bool ismax = threadIdx.x >= CGN;
        const float4* buf = ismax ? smax : ssum;

        float4 acc = buf[col];
        if (ismax) {
            #pragma unroll
            for (int j = 1; j < 8; ++j) {
                float4 v = buf[col + j * CGN];
                acc.x = fmaxf(acc.x, v.x); acc.y = fmaxf(acc.y, v.y);
                acc.z = fmaxf(acc.z, v.z); acc.w = fmaxf(acc.w, v.w);
            }
        } else {
            #pragma unroll
            for (int j = 1; j < 8; ++j) {
                float4 v = buf[col + j * CGN];
                acc.x += v.x; acc.y += v.y; acc.z += v.z; acc.w += v.w;
            }
        }

        float4 t = make_float4(tanhf(acc.x), tanhf(acc.y),
                               tanhf(acc.z), tanhf(acc.w));

        // Output row: [sum(256) | max(256)] -> 128 float4 per segment.
        float4* o = (float4*)out + (size_t)seg * (2 * NVROW)
                  + (ismax ? NVROW : 0) + half * CGN + col;
        *o = t;
    }
}

extern "C" void kernel_launch(void* const* d_in, const int* in_sizes, int n_in,
                              void* d_out, int out_size)
{
    const float* feat = (const float*)d_in[0];   // [N_ATOMS, 256] fp32
    const int*   mem  = (const int*)d_in[1];     // [N_ATOMS] int32, sorted
    float*       out  = (float*)d_out;           // [4096, 512] fp32

    const int n_atoms = in_sizes[1];

    boundary_kernel<<<(n_atoms + 255) / 256, 256>>>(mem, n_atoms);
    graph_gather_kernel<<<2 * BATCH, 256>>>((const float4*)feat, out);
}

// round 5
// speedup vs baseline: 1.1328x; 1.1328x over previous
#include <cuda_runtime.h>
#include <math.h>
#include <float.h>

#define D_FEAT 256
#define BATCH  4096
#define NV     (D_FEAT / 4)   // 64 float4 per row

// Segment boundary table: g_offsets[s] = first row index with membership >= s.
__device__ int g_offsets[BATCH + 1];

__global__ void boundary_kernel(const int* __restrict__ mem, int n_atoms)
{
    int i = blockIdx.x * blockDim.x + threadIdx.x;
    if (i >= n_atoms) return;
    int cur  = mem[i];
    int prev = (i == 0) ? -1 : mem[i - 1];
    for (int s = prev + 1; s <= cur; ++s) g_offsets[s] = i;
    if (i == n_atoms - 1) {
        for (int s = cur + 1; s <= BATCH; ++s) g_offsets[s] = n_atoms;
    }
}

__device__ __forceinline__ float4 ldcs4(const float4* p)
{
    return __ldcs(p);
}

// One CTA per segment (R3 mapping — best measured). 256 threads:
// cg = t & 63 (float4 column), ro = t >> 6 (4 row groups, row stride 4).
// Unroll 4: four independent 16B loads in flight per thread, two
// accumulator pairs to shorten dependency chains. smem reduce across
// the 4 row-groups, tanh, float4 streaming stores.
__global__ __launch_bounds__(256)
void graph_gather_kernel(const float4* __restrict__ feat,
                         float* __restrict__ out)
{
    const int seg   = blockIdx.x;
    const int start = g_offsets[seg];
    const int cnt   = g_offsets[seg + 1] - start;

    const int cg = threadIdx.x & (NV - 1);
    const int ro = threadIdx.x >> 6;

    const float4* __restrict__ p = feat + (size_t)start * NV + cg;

    float4 s0 = make_float4(0.f, 0.f, 0.f, 0.f);
    float4 s1 = make_float4(0.f, 0.f, 0.f, 0.f);
    float4 m0 = make_float4(-INFINITY, -INFINITY, -INFINITY, -INFINITY);
    float4 m1 = m0;

    int r = ro;
    for (; r + 12 < cnt; r += 16) {
        float4 a = ldcs4(&p[(size_t)(r     ) * NV]);
        float4 b = ldcs4(&p[(size_t)(r +  4) * NV]);
        float4 c = ldcs4(&p[(size_t)(r +  8) * NV]);
        float4 d = ldcs4(&p[(size_t)(r + 12) * NV]);
        s0.x += a.x + b.x;  s0.y += a.y + b.y;
        s0.z += a.z + b.z;  s0.w += a.w + b.w;
        s1.x += c.x + d.x;  s1.y += c.y + d.y;
        s1.z += c.z + d.z;  s1.w += c.w + d.w;
        m0.x = fmaxf(m0.x, fmaxf(a.x, b.x));
        m0.y = fmaxf(m0.y, fmaxf(a.y, b.y));
        m0.z = fmaxf(m0.z, fmaxf(a.z, b.z));
        m0.w = fmaxf(m0.w, fmaxf(a.w, b.w));
        m1.x = fmaxf(m1.x, fmaxf(c.x, d.x));
        m1.y = fmaxf(m1.y, fmaxf(c.y, d.y));
        m1.z = fmaxf(m1.z, fmaxf(c.z, d.z));
        m1.w = fmaxf(m1.w, fmaxf(c.w, d.w));
    }
    for (; r < cnt; r += 4) {
        float4 a = ldcs4(&p[(size_t)r * NV]);
        s0.x += a.x; s0.y += a.y; s0.z += a.z; s0.w += a.w;
        m0.x = fmaxf(m0.x, a.x); m0.y = fmaxf(m0.y, a.y);
        m0.z = fmaxf(m0.z, a.z); m0.w = fmaxf(m0.w, a.w);
    }

    float4 s, m;
    s.x = s0.x + s1.x; s.y = s0.y + s1.y;
    s.z = s0.z + s1.z; s.w = s0.w + s1.w;
    m.x = fmaxf(m0.x, m1.x); m.y = fmaxf(m0.y, m1.y);
    m.z = fmaxf(m0.z, m1.z); m.w = fmaxf(m0.w, m1.w);

    __shared__ float4 ssum[256];
    __shared__ float4 smax[256];
    ssum[threadIdx.x] = s;
    smax[threadIdx.x] = m;
    __syncthreads();

    // Threads 0-63 reduce sums, 64-127 reduce maxes (parallel halves).
    if (threadIdx.x < 128) {
        const int col    = threadIdx.x & (NV - 1);
        const bool ismax = threadIdx.x >= NV;
        const float4* buf = ismax ? smax : ssum;

        float4 v0 = buf[col],        v1 = buf[col + 64];
        float4 v2 = buf[col + 128],  v3 = buf[col + 192];

        float4 acc;
        if (ismax) {
            acc.x = fmaxf(fmaxf(v0.x, v1.x), fmaxf(v2.x, v3.x));
            acc.y = fmaxf(fmaxf(v0.y, v1.y), fmaxf(v2.y, v3.y));
            acc.z = fmaxf(fmaxf(v0.z, v1.z), fmaxf(v2.z, v3.z));
            acc.w = fmaxf(fmaxf(v0.w, v1.w), fmaxf(v2.w, v3.w));
        } else {
            acc.x = (v0.x + v1.x) + (v2.x + v3.x);
            acc.y = (v0.y + v1.y) + (v2.y + v3.y);
            acc.z = (v0.z + v1.z) + (v2.z + v3.z);
            acc.w = (v0.w + v1.w) + (v2.w + v3.w);
        }

        float4 t = make_float4(tanhf(acc.x), tanhf(acc.y),
                               tanhf(acc.z), tanhf(acc.w));

        float4* o = (float4*)out + (size_t)seg * (2 * NV)
                  + (ismax ? NV : 0) + col;
        __stcs(o, t);
    }
}

extern "C" void kernel_launch(void* const* d_in, const int* in_sizes, int n_in,
                              void* d_out, int out_size)
{
    const float* feat = (const float*)d_in[0];   // [N_ATOMS, 256] fp32
    const int*   mem  = (const int*)d_in[1];     // [N_ATOMS] int32, sorted
    float*       out  = (float*)d_out;           // [4096, 512] fp32

    const int n_atoms = in_sizes[1];

    boundary_kernel<<<(n_atoms + 255) / 256, 256>>>(mem, n_atoms);
    graph_gather_kernel<<<BATCH, 256>>>((const float4*)feat, out);
}